// round 2
// baseline (speedup 1.0000x reference)
#include <cuda_runtime.h>
#include <cstdint>

// Problem constants
#define BB   2
#define SS   2048
#define DD   1024
#define HH   16
#define DKK  64
#define MROWS (BB*SS)   // 4096

// ---------------------------------------------------------------------------
// Scratch (static device globals — allocation rules forbid cudaMalloc)
// ---------------------------------------------------------------------------
__device__ float g_Q[MROWS * DD];
__device__ float g_K[MROWS * DD];
__device__ float g_V[MROWS * DD];

// ---------------------------------------------------------------------------
// Helpers
// ---------------------------------------------------------------------------
__device__ __forceinline__ uint32_t f2tf(float f) {
    uint32_t u;
    asm("cvt.rna.tf32.f32 %0, %1;" : "=r"(u) : "f"(f));
    return u;
}

// D += A * B, m16n8k8 tf32. A row-major frag (4 regs), B col-major frag (2 regs),
// C/D fp32 (4 regs).
__device__ __forceinline__ void mma_tf32(float c[4], const uint32_t a[4], const uint32_t b[2]) {
    asm volatile(
        "mma.sync.aligned.m16n8k8.row.col.f32.tf32.tf32.f32 "
        "{%0,%1,%2,%3}, {%4,%5,%6,%7}, {%8,%9}, {%0,%1,%2,%3};"
        : "+f"(c[0]), "+f"(c[1]), "+f"(c[2]), "+f"(c[3])
        : "r"(a[0]), "r"(a[1]), "r"(a[2]), "r"(a[3]),
          "r"(b[0]), "r"(b[1]));
}

// ---------------------------------------------------------------------------
// Projection GEMM: Y = X @ W^T + bias
// X [4096,1024] row-major, W [1024,1024] row-major (n-major, k contiguous).
// Tile: BM=128, BN=128, BK=16, 256 threads (8 warps, 2x4), warp tile 64x32.
// gridDim.z in {0,1,2} selects (W_q->g_Q, W_k->g_K, W_v->g_V).
// Smem strides padded to 20 floats: frag-load bank = (20g + tig) mod 32, all
// 32 lanes distinct -> conflict-free.
// ---------------------------------------------------------------------------
#define PM 128
#define PN 128
#define PK 16
#define PSTR 20

__global__ __launch_bounds__(256) void proj_kernel(
    const float* __restrict__ X,
    const float* __restrict__ W0, const float* __restrict__ bv0,
    const float* __restrict__ W1, const float* __restrict__ bv1,
    const float* __restrict__ W2, const float* __restrict__ bv2)
{
    __shared__ uint32_t As[2][PM * PSTR];
    __shared__ uint32_t Bs[2][PN * PSTR];

    const int z = blockIdx.z;
    const float* __restrict__ Wp = (z == 0) ? W0 : (z == 1) ? W1 : W2;
    const float* __restrict__ bp = (z == 0) ? bv0 : (z == 1) ? bv1 : bv2;
    float* __restrict__ Yp       = (z == 0) ? g_Q : (z == 1) ? g_K : g_V;

    const int bm = blockIdx.y * PM;
    const int bn = blockIdx.x * PN;

    const int t    = threadIdx.x;
    const int w    = t >> 5;
    const int lane = t & 31;
    const int g    = lane >> 2;
    const int tig  = lane & 3;
    const int wm   = (w >> 2) * 64;  // warp m offset (0 or 64)
    const int wn   = (w & 3) * 32;   // warp n offset (0,32,64,96)

    // global load mapping: id = t + 256*i -> row = id/4 (0..127), kq = id%4
    const int lrow = t >> 2;
    const int lkq  = (t & 3) * 4;

    float4 av[2], bvv[2];

    auto gload = [&](int kb) {
        #pragma unroll
        for (int i = 0; i < 2; i++) {
            int row = lrow + i * 64;
            av[i]  = *(const float4*)&X [(size_t)(bm + row) * DD + kb + lkq];
            bvv[i] = *(const float4*)&Wp[(size_t)(bn + row) * DD + kb + lkq];
        }
    };
    auto sstore = [&](int buf) {
        #pragma unroll
        for (int i = 0; i < 2; i++) {
            int row = lrow + i * 64;
            uint4 ua = make_uint4(f2tf(av[i].x),  f2tf(av[i].y),  f2tf(av[i].z),  f2tf(av[i].w));
            uint4 ub = make_uint4(f2tf(bvv[i].x), f2tf(bvv[i].y), f2tf(bvv[i].z), f2tf(bvv[i].w));
            *(uint4*)&As[buf][row * PSTR + lkq] = ua;
            *(uint4*)&Bs[buf][row * PSTR + lkq] = ub;
        }
    };

    float acc[4][4][4];
    #pragma unroll
    for (int i = 0; i < 4; i++)
        #pragma unroll
        for (int j = 0; j < 4; j++)
            #pragma unroll
            for (int e = 0; e < 4; e++) acc[i][j][e] = 0.f;

    // prologue
    gload(0);
    sstore(0);
    __syncthreads();

    const int KT = DD / PK;  // 64
    for (int kt = 0; kt < KT; kt++) {
        const int cur = kt & 1;
        if (kt + 1 < KT) gload((kt + 1) * PK);

        #pragma unroll
        for (int ks = 0; ks < 2; ks++) {
            const int k0 = ks * 8;
            uint32_t af[4][4], bf[4][2];
            #pragma unroll
            for (int i = 0; i < 4; i++) {
                int m0 = wm + i * 16;
                af[i][0] = As[cur][(m0 + g)     * PSTR + k0 + tig];
                af[i][1] = As[cur][(m0 + g + 8) * PSTR + k0 + tig];
                af[i][2] = As[cur][(m0 + g)     * PSTR + k0 + tig + 4];
                af[i][3] = As[cur][(m0 + g + 8) * PSTR + k0 + tig + 4];
            }
            #pragma unroll
            for (int j = 0; j < 4; j++) {
                int n0 = wn + j * 8;
                bf[j][0] = Bs[cur][(n0 + g) * PSTR + k0 + tig];
                bf[j][1] = Bs[cur][(n0 + g) * PSTR + k0 + tig + 4];
            }
            #pragma unroll
            for (int i = 0; i < 4; i++)
                #pragma unroll
                for (int j = 0; j < 4; j++)
                    mma_tf32(acc[i][j], af[i], bf[j]);
        }

        if (kt + 1 < KT) sstore(cur ^ 1);
        __syncthreads();
    }

    // epilogue: add bias, write Y (float2 stores)
    #pragma unroll
    for (int j = 0; j < 4; j++) {
        const int n0 = bn + wn + j * 8 + 2 * tig;
        const float b0 = bp[n0], b1 = bp[n0 + 1];
        #pragma unroll
        for (int i = 0; i < 4; i++) {
            const int m0 = bm + wm + i * 16;
            *(float2*)&Yp[(size_t)(m0 + g)     * DD + n0] =
                make_float2(acc[i][j][0] + b0, acc[i][j][1] + b1);
            *(float2*)&Yp[(size_t)(m0 + g + 8) * DD + n0] =
                make_float2(acc[i][j][2] + b0, acc[i][j][3] + b1);
        }
    }
}

// ---------------------------------------------------------------------------
// Causal flash attention.
// Grid: (32 q-tiles, 32 batch*head). CTA = 128 threads = 4 warps, each warp
// owns 16 q rows. Q frags live in registers (pre-scaled by 1/sqrt(DK)).
// K tile smem stride 68 (bank = 4g+tig: conflict-free), V tile stride 72
// (bank = 8*tig+g: conflict-free). P aliases the K region (K is dead after
// the QK mma; a CTA barrier separates the phases) to stay < 48KB static smem.
// ---------------------------------------------------------------------------
#define KSTR 68
#define VSTR 72

__global__ __launch_bounds__(128) void attn_kernel(float* __restrict__ out)
{
    __shared__ uint32_t Ks[64 * KSTR];  // K tile; re-used as P after QK phase
    __shared__ uint32_t Vs[64 * VSTR];

    const int qtile = blockIdx.x;        // 0..31
    const int bh    = blockIdx.y;        // 0..31
    const int b     = bh >> 4;
    const int h     = bh & 15;
    const int qbase = qtile * 64;
    const int browQ = b * SS + qbase;    // global row base
    const int hc    = h * DKK;           // head column offset

    const int t    = threadIdx.x;
    const int w    = t >> 5;
    const int lane = t & 31;
    const int g    = lane >> 2;
    const int tig  = lane & 3;

    // Q fragments, pre-scaled by 1/sqrt(64)
    const float scale = 0.125f;
    uint32_t qa[8][4];
    {
        const float* Qr0 = g_Q + (size_t)(browQ + w * 16 + g) * DD + hc;
        const float* Qr1 = Qr0 + 8 * DD;
        #pragma unroll
        for (int kk = 0; kk < 8; kk++) {
            qa[kk][0] = f2tf(Qr0[kk * 8 + tig]     * scale);
            qa[kk][1] = f2tf(Qr1[kk * 8 + tig]     * scale);
            qa[kk][2] = f2tf(Qr0[kk * 8 + tig + 4] * scale);
            qa[kk][3] = f2tf(Qr1[kk * 8 + tig + 4] * scale);
        }
    }

    float o[8][4];
    #pragma unroll
    for (int d = 0; d < 8; d++)
        #pragma unroll
        for (int e = 0; e < 4; e++) o[d][e] = 0.f;
    float mprev0 = -1e30f, mprev1 = -1e30f;
    float l0 = 0.f, l1 = 0.f;

    for (int j = 0; j <= qtile; j++) {
        const int kvbase = b * SS + j * 64;

        __syncthreads();  // previous tile's smem consumers done
        // stage K and V tiles (tf32-rounded): 64 rows x 16 float4 each
        #pragma unroll
        for (int i = 0; i < 8; i++) {
            int id = t + 128 * i;
            int r  = id >> 4;
            int q4 = (id & 15) * 4;
            float4 k4 = *(const float4*)&g_K[(size_t)(kvbase + r) * DD + hc + q4];
            float4 v4 = *(const float4*)&g_V[(size_t)(kvbase + r) * DD + hc + q4];
            *(uint4*)&Ks[r * KSTR + q4] =
                make_uint4(f2tf(k4.x), f2tf(k4.y), f2tf(k4.z), f2tf(k4.w));
            *(uint4*)&Vs[r * VSTR + q4] =
                make_uint4(f2tf(v4.x), f2tf(v4.y), f2tf(v4.z), f2tf(v4.w));
        }
        __syncthreads();

        // S = Q K^T  (scores already scaled via Q)
        float s[8][4];
        #pragma unroll
        for (int n = 0; n < 8; n++) { s[n][0] = s[n][1] = s[n][2] = s[n][3] = 0.f; }
        #pragma unroll
        for (int kk = 0; kk < 8; kk++) {
            #pragma unroll
            for (int n = 0; n < 8; n++) {
                uint32_t bf[2];
                bf[0] = Ks[(n * 8 + g) * KSTR + kk * 8 + tig];
                bf[1] = Ks[(n * 8 + g) * KSTR + kk * 8 + tig + 4];
                mma_tf32(s[n], qa[kk], bf);
            }
        }

        __syncthreads();  // all QK reads of Ks done; Ks region becomes P

        // causal mask on the diagonal tile
        if (j == qtile) {
            const int r0 = w * 16 + g, r1 = r0 + 8;
            #pragma unroll
            for (int n = 0; n < 8; n++) {
                int c = n * 8 + 2 * tig;
                if (c     > r0) s[n][0] = -1e30f;
                if (c + 1 > r0) s[n][1] = -1e30f;
                if (c     > r1) s[n][2] = -1e30f;
                if (c + 1 > r1) s[n][3] = -1e30f;
            }
        }

        // online softmax
        float mt0 = -1e30f, mt1 = -1e30f;
        #pragma unroll
        for (int n = 0; n < 8; n++) {
            mt0 = fmaxf(mt0, fmaxf(s[n][0], s[n][1]));
            mt1 = fmaxf(mt1, fmaxf(s[n][2], s[n][3]));
        }
        mt0 = fmaxf(mt0, __shfl_xor_sync(0xffffffffu, mt0, 1));
        mt0 = fmaxf(mt0, __shfl_xor_sync(0xffffffffu, mt0, 2));
        mt1 = fmaxf(mt1, __shfl_xor_sync(0xffffffffu, mt1, 1));
        mt1 = fmaxf(mt1, __shfl_xor_sync(0xffffffffu, mt1, 2));

        const float mnew0  = fmaxf(mprev0, mt0);
        const float mnew1  = fmaxf(mprev1, mt1);
        const float alpha0 = __expf(mprev0 - mnew0);
        const float alpha1 = __expf(mprev1 - mnew1);
        mprev0 = mnew0;
        mprev1 = mnew1;

        uint32_t* Ps = &Ks[(w * 16) * KSTR];  // warp-private P slice
        float rs0 = 0.f, rs1 = 0.f;
        #pragma unroll
        for (int n = 0; n < 8; n++) {
            float p0 = __expf(s[n][0] - mnew0);
            float p1 = __expf(s[n][1] - mnew0);
            float p2 = __expf(s[n][2] - mnew1);
            float p3 = __expf(s[n][3] - mnew1);
            rs0 += p0 + p1;
            rs1 += p2 + p3;
            *(uint2*)&Ps[g       * KSTR + n * 8 + 2 * tig] = make_uint2(f2tf(p0), f2tf(p1));
            *(uint2*)&Ps[(g + 8) * KSTR + n * 8 + 2 * tig] = make_uint2(f2tf(p2), f2tf(p3));
        }
        rs0 += __shfl_xor_sync(0xffffffffu, rs0, 1);
        rs0 += __shfl_xor_sync(0xffffffffu, rs0, 2);
        rs1 += __shfl_xor_sync(0xffffffffu, rs1, 1);
        rs1 += __shfl_xor_sync(0xffffffffu, rs1, 2);
        l0 = l0 * alpha0 + rs0;
        l1 = l1 * alpha1 + rs1;

        #pragma unroll
        for (int d = 0; d < 8; d++) {
            o[d][0] *= alpha0; o[d][1] *= alpha0;
            o[d][2] *= alpha1; o[d][3] *= alpha1;
        }

        __syncwarp();  // warp-private P stores visible to warp's loads

        // O += P V
        #pragma unroll
        for (int kk = 0; kk < 8; kk++) {
            uint32_t af[4];
            af[0] = Ps[g       * KSTR + kk * 8 + tig];
            af[1] = Ps[(g + 8) * KSTR + kk * 8 + tig];
            af[2] = Ps[g       * KSTR + kk * 8 + tig + 4];
            af[3] = Ps[(g + 8) * KSTR + kk * 8 + tig + 4];
            #pragma unroll
            for (int d = 0; d < 8; d++) {
                uint32_t bf[2];
                bf[0] = Vs[(kk * 8 + tig)     * VSTR + d * 8 + g];
                bf[1] = Vs[(kk * 8 + tig + 4) * VSTR + d * 8 + g];
                mma_tf32(o[d], af, bf);
            }
        }
    }

    // normalize and write output
    const float inv0 = 1.f / l0;
    const float inv1 = 1.f / l1;
    float* O0 = out + (size_t)(browQ + w * 16 + g) * DD + hc;
    float* O1 = O0 + 8 * DD;
    #pragma unroll
    for (int d = 0; d < 8; d++) {
        *(float2*)&O0[d * 8 + 2 * tig] = make_float2(o[d][0] * inv0, o[d][1] * inv0);
        *(float2*)&O1[d * 8 + 2 * tig] = make_float2(o[d][2] * inv1, o[d][3] * inv1);
    }
}

// ---------------------------------------------------------------------------
// Launch
// ---------------------------------------------------------------------------
extern "C" void kernel_launch(void* const* d_in, const int* in_sizes, int n_in,
                              void* d_out, int out_size)
{
    const float* x  = (const float*)d_in[0];
    const float* Wq = (const float*)d_in[1];
    const float* bq = (const float*)d_in[2];
    const float* Wk = (const float*)d_in[3];
    const float* bk = (const float*)d_in[4];
    const float* Wv = (const float*)d_in[5];
    const float* bv = (const float*)d_in[6];
    float* out = (float*)d_out;

    proj_kernel<<<dim3(DD / PN, MROWS / PM, 3), 256>>>(x, Wq, bq, Wk, bk, Wv, bv);
    attn_kernel<<<dim3(SS / 64, BB * HH), 128>>>(out);
}

// round 4
// speedup vs baseline: 1.0738x; 1.0738x over previous
#include <cuda_runtime.h>
#include <cstdint>

// Problem constants
#define BB   2
#define SS   2048
#define DD   1024
#define HH   16
#define DKK  64
#define MROWS (BB*SS)   // 4096

// ---------------------------------------------------------------------------
// Scratch (static device globals — allocation rules forbid cudaMalloc)
// ---------------------------------------------------------------------------
__device__ float g_Q[MROWS * DD];
__device__ float g_K[MROWS * DD];
__device__ float g_V[MROWS * DD];

// ---------------------------------------------------------------------------
// Helpers
// ---------------------------------------------------------------------------
__device__ __forceinline__ uint32_t f2tf(float f) {
    uint32_t u;
    asm("cvt.rna.tf32.f32 %0, %1;" : "=r"(u) : "f"(f));
    return u;
}

__device__ __forceinline__ void mma_tf32(float c[4], const uint32_t a[4], const uint32_t b[2]) {
    asm volatile(
        "mma.sync.aligned.m16n8k8.row.col.f32.tf32.tf32.f32 "
        "{%0,%1,%2,%3}, {%4,%5,%6,%7}, {%8,%9}, {%0,%1,%2,%3};"
        : "+f"(c[0]), "+f"(c[1]), "+f"(c[2]), "+f"(c[3])
        : "r"(a[0]), "r"(a[1]), "r"(a[2]), "r"(a[3]),
          "r"(b[0]), "r"(b[1]));
}

// ---------------------------------------------------------------------------
// Projection GEMM: Y = X @ W^T + bias
// CTA tile 128x128, BK=16, 128 threads = 4 warps (2x2), warp tile 64x64.
// LDS per mma: (16 A + 16 B) / 32 mmas = 1.0 (was 1.5).
// ---------------------------------------------------------------------------
#define PM 128
#define PN 128
#define PK 16
#define PSTR 20

__global__ __launch_bounds__(128) void proj_kernel(
    const float* __restrict__ X,
    const float* __restrict__ W0, const float* __restrict__ bv0,
    const float* __restrict__ W1, const float* __restrict__ bv1,
    const float* __restrict__ W2, const float* __restrict__ bv2)
{
    __shared__ uint32_t As[2][PM * PSTR];
    __shared__ uint32_t Bs[2][PN * PSTR];

    const int z = blockIdx.z;
    const float* __restrict__ Wp = (z == 0) ? W0 : (z == 1) ? W1 : W2;
    const float* __restrict__ bp = (z == 0) ? bv0 : (z == 1) ? bv1 : bv2;
    float* __restrict__ Yp       = (z == 0) ? g_Q : (z == 1) ? g_K : g_V;

    const int bm = blockIdx.y * PM;
    const int bn = blockIdx.x * PN;

    const int t    = threadIdx.x;
    const int w    = t >> 5;
    const int lane = t & 31;
    const int g    = lane >> 2;
    const int tig  = lane & 3;
    const int wm   = (w >> 1) * 64;  // warp m offset (0 or 64)
    const int wn   = (w & 1)  * 64;  // warp n offset (0 or 64)

    // global load mapping: id = t + 128*i -> row = id/4 (0..127), kq = (id%4)*4
    const int lrow = t >> 2;
    const int lkq  = (t & 3) * 4;

    float4 av[4], bvv[4];

    auto gload = [&](int kb) {
        #pragma unroll
        for (int i = 0; i < 4; i++) {
            int row = lrow + i * 32;
            av[i]  = *(const float4*)&X [(size_t)(bm + row) * DD + kb + lkq];
            bvv[i] = *(const float4*)&Wp[(size_t)(bn + row) * DD + kb + lkq];
        }
    };
    auto sstore = [&](int buf) {
        #pragma unroll
        for (int i = 0; i < 4; i++) {
            int row = lrow + i * 32;
            uint4 ua = make_uint4(f2tf(av[i].x),  f2tf(av[i].y),  f2tf(av[i].z),  f2tf(av[i].w));
            uint4 ub = make_uint4(f2tf(bvv[i].x), f2tf(bvv[i].y), f2tf(bvv[i].z), f2tf(bvv[i].w));
            *(uint4*)&As[buf][row * PSTR + lkq] = ua;
            *(uint4*)&Bs[buf][row * PSTR + lkq] = ub;
        }
    };

    float acc[4][8][4];
    #pragma unroll
    for (int i = 0; i < 4; i++)
        #pragma unroll
        for (int j = 0; j < 8; j++)
            #pragma unroll
            for (int e = 0; e < 4; e++) acc[i][j][e] = 0.f;

    gload(0);
    sstore(0);
    __syncthreads();

    const int KT = DD / PK;  // 64
    for (int kt = 0; kt < KT; kt++) {
        const int cur = kt & 1;
        if (kt + 1 < KT) gload((kt + 1) * PK);

        #pragma unroll
        for (int ks = 0; ks < 2; ks++) {
            const int k0 = ks * 8;
            uint32_t af[4][4], bf[8][2];
            #pragma unroll
            for (int i = 0; i < 4; i++) {
                int m0 = wm + i * 16;
                af[i][0] = As[cur][(m0 + g)     * PSTR + k0 + tig];
                af[i][1] = As[cur][(m0 + g + 8) * PSTR + k0 + tig];
                af[i][2] = As[cur][(m0 + g)     * PSTR + k0 + tig + 4];
                af[i][3] = As[cur][(m0 + g + 8) * PSTR + k0 + tig + 4];
            }
            #pragma unroll
            for (int j = 0; j < 8; j++) {
                int n0 = wn + j * 8;
                bf[j][0] = Bs[cur][(n0 + g) * PSTR + k0 + tig];
                bf[j][1] = Bs[cur][(n0 + g) * PSTR + k0 + tig + 4];
            }
            #pragma unroll
            for (int i = 0; i < 4; i++)
                #pragma unroll
                for (int j = 0; j < 8; j++)
                    mma_tf32(acc[i][j], af[i], bf[j]);
        }

        if (kt + 1 < KT) sstore(cur ^ 1);
        __syncthreads();
    }

    // epilogue: add bias, write Y
    #pragma unroll
    for (int j = 0; j < 8; j++) {
        const int n0 = bn + wn + j * 8 + 2 * tig;
        const float b0 = bp[n0], b1 = bp[n0 + 1];
        #pragma unroll
        for (int i = 0; i < 4; i++) {
            const int m0 = bm + wm + i * 16;
            *(float2*)&Yp[(size_t)(m0 + g)     * DD + n0] =
                make_float2(acc[i][j][0] + b0, acc[i][j][1] + b1);
            *(float2*)&Yp[(size_t)(m0 + g + 8) * DD + n0] =
                make_float2(acc[i][j][2] + b0, acc[i][j][3] + b1);
        }
    }
}

// ---------------------------------------------------------------------------
// Causal flash attention, v2.
// CTA: 128 threads = 4 warps; Q tile 128 rows; warp owns 32 rows (2 frag
// blocks sharing every K/V B-frag load). KV tile 64. Q staged in smem
// (pre-scaled tf32), K/V staged per tile, P written to smem (warps 0/1 alias
// the dead K region, warps 2/3 use a dedicated region). Dynamic smem 88KB,
// 2 CTAs/SM. Heavy q-tiles launch first (reversed blockIdx.x).
// ---------------------------------------------------------------------------
#define QSTR 68
#define KSTR 68
#define VSTR 72
#define ATTN_DYN_WORDS (128*QSTR + 64*KSTR + 64*VSTR + 64*KSTR)
#define ATTN_DYN_BYTES (ATTN_DYN_WORDS * 4)

__global__ __launch_bounds__(128) void attn_kernel(float* __restrict__ out)
{
    extern __shared__ uint32_t dyn[];
    uint32_t* Qs = dyn;                       // 128 x QSTR
    uint32_t* Ks = Qs + 128 * QSTR;           // 64 x KSTR (aliased by P, warps 0/1)
    uint32_t* Vs = Ks + 64 * KSTR;            // 64 x VSTR
    uint32_t* Px = Vs + 64 * VSTR;            // 64 x KSTR (P, warps 2/3)

    const int qtile = gridDim.x - 1 - (int)blockIdx.x;  // 0..15, heavy first
    const int bh    = blockIdx.y;
    const int b     = bh >> 4;
    const int h     = bh & 15;
    const int browQ = b * SS + qtile * 128;
    const int hc    = h * DKK;

    const int t    = threadIdx.x;
    const int w    = t >> 5;
    const int lane = t & 31;
    const int g    = lane >> 2;
    const int tig  = lane & 3;
    const int qr   = w * 32;   // warp's row base within the 128-row q tile

    // stage Q tile once (pre-scaled by 1/sqrt(64), tf32)
    #pragma unroll
    for (int i = 0; i < 16; i++) {
        int id = t + 128 * i;
        int r  = id >> 4;
        int c4 = (id & 15) * 4;
        float4 q4 = *(const float4*)&g_Q[(size_t)(browQ + r) * DD + hc + c4];
        *(uint4*)&Qs[r * QSTR + c4] = make_uint4(
            f2tf(q4.x * 0.125f), f2tf(q4.y * 0.125f),
            f2tf(q4.z * 0.125f), f2tf(q4.w * 0.125f));
    }

    uint32_t* Ps = (w < 2) ? &Ks[(w * 32) * KSTR] : &Px[((w - 2) * 32) * KSTR];

    float o[2][8][4];
    #pragma unroll
    for (int blk = 0; blk < 2; blk++)
        #pragma unroll
        for (int d = 0; d < 8; d++)
            #pragma unroll
            for (int e = 0; e < 4; e++) o[blk][d][e] = 0.f;
    float mrun[2][2] = {{-1e30f, -1e30f}, {-1e30f, -1e30f}};
    float lrun[2][2] = {{0.f, 0.f}, {0.f, 0.f}};

    const int jend = 2 * qtile + 1;
    for (int j = 0; j <= jend; j++) {
        const int kvbase = b * SS + j * 64;

        __syncthreads();  // previous tile's P/V consumers done
        #pragma unroll
        for (int i = 0; i < 8; i++) {
            int id = t + 128 * i;
            int r  = id >> 4;
            int c4 = (id & 15) * 4;
            float4 k4 = *(const float4*)&g_K[(size_t)(kvbase + r) * DD + hc + c4];
            float4 v4 = *(const float4*)&g_V[(size_t)(kvbase + r) * DD + hc + c4];
            *(uint4*)&Ks[r * KSTR + c4] =
                make_uint4(f2tf(k4.x), f2tf(k4.y), f2tf(k4.z), f2tf(k4.w));
            *(uint4*)&Vs[r * VSTR + c4] =
                make_uint4(f2tf(v4.x), f2tf(v4.y), f2tf(v4.z), f2tf(v4.w));
        }
        __syncthreads();

        // S = Q K^T : every B-frag shared by 2 row blocks
        float s[2][8][4];
        #pragma unroll
        for (int blk = 0; blk < 2; blk++)
            #pragma unroll
            for (int n = 0; n < 8; n++)
                #pragma unroll
                for (int e = 0; e < 4; e++) s[blk][n][e] = 0.f;

        #pragma unroll
        for (int kk = 0; kk < 8; kk++) {
            uint32_t af[2][4];
            #pragma unroll
            for (int blk = 0; blk < 2; blk++) {
                const int r0 = qr + blk * 16;
                af[blk][0] = Qs[(r0 + g)     * QSTR + kk * 8 + tig];
                af[blk][1] = Qs[(r0 + g + 8) * QSTR + kk * 8 + tig];
                af[blk][2] = Qs[(r0 + g)     * QSTR + kk * 8 + tig + 4];
                af[blk][3] = Qs[(r0 + g + 8) * QSTR + kk * 8 + tig + 4];
            }
            #pragma unroll
            for (int n = 0; n < 8; n++) {
                uint32_t bf[2];
                bf[0] = Ks[(n * 8 + g) * KSTR + kk * 8 + tig];
                bf[1] = Ks[(n * 8 + g) * KSTR + kk * 8 + tig + 4];
                mma_tf32(s[0][n], af[0], bf);
                mma_tf32(s[1][n], af[1], bf);
            }
        }

        __syncthreads();  // all QK reads of Ks done; Ks region becomes P

        // causal mask (only the two diagonal-adjacent tiles need it)
        if (j >= 2 * qtile) {
            #pragma unroll
            for (int blk = 0; blk < 2; blk++) {
                const int r0 = qtile * 128 + qr + blk * 16 + g;
                const int r1 = r0 + 8;
                #pragma unroll
                for (int n = 0; n < 8; n++) {
                    const int c = j * 64 + n * 8 + 2 * tig;
                    if (c     > r0) s[blk][n][0] = -1e30f;
                    if (c + 1 > r0) s[blk][n][1] = -1e30f;
                    if (c     > r1) s[blk][n][2] = -1e30f;
                    if (c + 1 > r1) s[blk][n][3] = -1e30f;
                }
            }
        }

        // online softmax per row block
        #pragma unroll
        for (int blk = 0; blk < 2; blk++) {
            float mt0 = -1e30f, mt1 = -1e30f;
            #pragma unroll
            for (int n = 0; n < 8; n++) {
                mt0 = fmaxf(mt0, fmaxf(s[blk][n][0], s[blk][n][1]));
                mt1 = fmaxf(mt1, fmaxf(s[blk][n][2], s[blk][n][3]));
            }
            mt0 = fmaxf(mt0, __shfl_xor_sync(0xffffffffu, mt0, 1));
            mt0 = fmaxf(mt0, __shfl_xor_sync(0xffffffffu, mt0, 2));
            mt1 = fmaxf(mt1, __shfl_xor_sync(0xffffffffu, mt1, 1));
            mt1 = fmaxf(mt1, __shfl_xor_sync(0xffffffffu, mt1, 2));

            const float mnew0  = fmaxf(mrun[blk][0], mt0);
            const float mnew1  = fmaxf(mrun[blk][1], mt1);
            const float alpha0 = __expf(mrun[blk][0] - mnew0);
            const float alpha1 = __expf(mrun[blk][1] - mnew1);
            mrun[blk][0] = mnew0;
            mrun[blk][1] = mnew1;

            float rs0 = 0.f, rs1 = 0.f;
            #pragma unroll
            for (int n = 0; n < 8; n++) {
                float p0 = __expf(s[blk][n][0] - mnew0);
                float p1 = __expf(s[blk][n][1] - mnew0);
                float p2 = __expf(s[blk][n][2] - mnew1);
                float p3 = __expf(s[blk][n][3] - mnew1);
                rs0 += p0 + p1;
                rs1 += p2 + p3;
                *(uint2*)&Ps[(blk * 16 + g)     * KSTR + n * 8 + 2 * tig] =
                    make_uint2(f2tf(p0), f2tf(p1));
                *(uint2*)&Ps[(blk * 16 + g + 8) * KSTR + n * 8 + 2 * tig] =
                    make_uint2(f2tf(p2), f2tf(p3));
            }
            rs0 += __shfl_xor_sync(0xffffffffu, rs0, 1);
            rs0 += __shfl_xor_sync(0xffffffffu, rs0, 2);
            rs1 += __shfl_xor_sync(0xffffffffu, rs1, 1);
            rs1 += __shfl_xor_sync(0xffffffffu, rs1, 2);
            lrun[blk][0] = lrun[blk][0] * alpha0 + rs0;
            lrun[blk][1] = lrun[blk][1] * alpha1 + rs1;

            #pragma unroll
            for (int d = 0; d < 8; d++) {
                o[blk][d][0] *= alpha0; o[blk][d][1] *= alpha0;
                o[blk][d][2] *= alpha1; o[blk][d][3] *= alpha1;
            }
        }

        __syncwarp();  // warp-private P stores visible to this warp's loads

        // O += P V : every V B-frag shared by 2 row blocks
        #pragma unroll
        for (int kk = 0; kk < 8; kk++) {
            uint32_t af[2][4];
            #pragma unroll
            for (int blk = 0; blk < 2; blk++) {
                const int r0 = blk * 16;
                af[blk][0] = Ps[(r0 + g)     * KSTR + kk * 8 + tig];
                af[blk][1] = Ps[(r0 + g + 8) * KSTR + kk * 8 + tig];
                af[blk][2] = Ps[(r0 + g)     * KSTR + kk * 8 + tig + 4];
                af[blk][3] = Ps[(r0 + g + 8) * KSTR + kk * 8 + tig + 4];
            }
            #pragma unroll
            for (int d = 0; d < 8; d++) {
                uint32_t bf[2];
                bf[0] = Vs[(kk * 8 + tig)     * VSTR + d * 8 + g];
                bf[1] = Vs[(kk * 8 + tig + 4) * VSTR + d * 8 + g];
                mma_tf32(o[0][d], af[0], bf);
                mma_tf32(o[1][d], af[1], bf);
            }
        }
    }

    // normalize and write output
    #pragma unroll
    for (int blk = 0; blk < 2; blk++) {
        const float inv0 = 1.f / lrun[blk][0];
        const float inv1 = 1.f / lrun[blk][1];
        float* O0 = out + (size_t)(browQ + qr + blk * 16 + g) * DD + hc;
        float* O1 = O0 + 8 * DD;
        #pragma unroll
        for (int d = 0; d < 8; d++) {
            *(float2*)&O0[d * 8 + 2 * tig] =
                make_float2(o[blk][d][0] * inv0, o[blk][d][1] * inv0);
            *(float2*)&O1[d * 8 + 2 * tig] =
                make_float2(o[blk][d][2] * inv1, o[blk][d][3] * inv1);
        }
    }
}

// ---------------------------------------------------------------------------
// Launch
// ---------------------------------------------------------------------------
extern "C" void kernel_launch(void* const* d_in, const int* in_sizes, int n_in,
                              void* d_out, int out_size)
{
    const float* x  = (const float*)d_in[0];
    const float* Wq = (const float*)d_in[1];
    const float* bq = (const float*)d_in[2];
    const float* Wk = (const float*)d_in[3];
    const float* bk = (const float*)d_in[4];
    const float* Wv = (const float*)d_in[5];
    const float* bv = (const float*)d_in[6];
    float* out = (float*)d_out;

    cudaFuncSetAttribute(attn_kernel,
                         cudaFuncAttributeMaxDynamicSharedMemorySize,
                         ATTN_DYN_BYTES);

    proj_kernel<<<dim3(DD / PN, MROWS / PM, 3), 128>>>(x, Wq, bq, Wk, bk, Wv, bv);
    attn_kernel<<<dim3(SS / 128, BB * HH), 128, ATTN_DYN_BYTES>>>(out);
}